// round 13
// baseline (speedup 1.0000x reference)
#include <cuda_runtime.h>
#include <cuda_fp16.h>

// HDBLUT 2x superresolution, GB300 sm_103a. Round 13:
//  R12 + shuffle-distributed patch load: the 30 packed words a warp-tile
//  needs (5 words x 6 rows) are fetched with ONE warp-wide LDG.32 and
//  redistributed with 12 SHFLs -> LSU ops/iter 40 -> 29.

#define NN 2048
#define NTILES (1024 * 64)        // row-pairs x 32-col tiles
#define THREADS 640
#define WARPS_PER_CTA (THREADS / 32)
#define LUT_E (3 * 4096)
#define PSTRIDE 260
#define PWORDS 257
#define SMEM_BYTES (LUT_E * 8)

__device__ __align__(16) uint2 g_lut[LUT_E];   // half4 per entry, 96 KB
__device__ unsigned g_pimg[NN * PSTRIDE];      // nibble-packed image

__device__ __forceinline__ int refl(int t) {
    t = (t < 0) ? -t : t;
    return (t >= NN) ? (2 * NN - 2 - t) : t;
}

__device__ __forceinline__ __half2 u2h(unsigned u) {
    return *reinterpret_cast<__half2*>(&u);
}

// blocks 0..2047: pack one image row each (int4 loads via smem staging)
// blocks 2048..: convert LUT float4 -> half4 (1/3 folded)
__global__ void hdblut_prelude(const int* __restrict__ img,
                               const float4* __restrict__ w)
{
    __shared__ int srow[2056];
    const int tid = threadIdx.x;

    if (blockIdx.x < NN) {
        const int r = blockIdx.x;
        const int4* row4 = reinterpret_cast<const int4*>(img + (size_t)r * NN);
        #pragma unroll
        for (int k = 0; k < 2; k++) {
            int i = tid + k * 256;
            int4 v = __ldg(row4 + i);
            srow[2 + i * 4 + 0] = v.x;
            srow[2 + i * 4 + 1] = v.y;
            srow[2 + i * 4 + 2] = v.z;
            srow[2 + i * 4 + 3] = v.w;
        }
        __syncthreads();
        if (tid == 0) {
            srow[0] = srow[4];
            srow[1] = srow[3];
            #pragma unroll
            for (int i = 0; i < 6; i++)
                srow[2050 + i] = srow[2048 - i];
        }
        __syncthreads();
        for (int wi = tid; wi < PWORDS; wi += 256) {
            const int* s = srow + wi * 8;
            unsigned val = 0;
            #pragma unroll
            for (int j = 0; j < 8; j++)
                val |= (unsigned)(s[j] & 15) << (4 * j);
            g_pimg[(size_t)r * PSTRIDE + wi] = val;
        }
    } else {
        int gid = (blockIdx.x - NN) * blockDim.x + tid;
        if (gid < LUT_E) {
            float4 v = __ldg(w + gid);
            const float s = 1.0f / 3.0f;
            __half2 lo = __floats2half2_rn(v.x * s, v.y * s);
            __half2 hi = __floats2half2_rn(v.z * s, v.w * s);
            uint2 u;
            u.x = *reinterpret_cast<unsigned*>(&lo);
            u.y = *reinterpret_cast<unsigned*>(&hi);
            g_lut[gid] = u;
        }
    }
}

__global__ __launch_bounds__(THREADS, 2)
void hdblut_main(float2* __restrict__ out)
{
    extern __shared__ uint2 slut[];   // 96 KB fp16 LUT

    {
        uint4*       s4 = reinterpret_cast<uint4*>(slut);
        const uint4* g4 = reinterpret_cast<const uint4*>(g_lut);
        for (int i = threadIdx.x; i < LUT_E / 2; i += THREADS)
            s4[i] = g4[i];
    }
    __syncthreads();

    const char* lutb = reinterpret_cast<const char*>(slut);
    const int warp = threadIdx.x >> 5;
    const int lane = threadIdx.x & 31;
    const int gwarp  = blockIdx.x * WARPS_PER_CTA + warp;
    const int nwarps = gridDim.x * WARPS_PER_CTA;

    // lane's loader assignment: row li/5 (0..5), word offset li%5 (0..4)
    const int lrow = (lane < 30) ? (lane / 5) : 0;
    const int lwrd = (lane < 30) ? (lane - lrow * 5) : 0;
    const int ssub = lane >> 3;           // word sub-index within 5-word span
    const int sh   = (lane & 7) * 4;      // nibble shift within word

    for (int t = gwarp; t < NTILES; t += nwarps) {
        const int I  = (t >> 6) << 1;       // low-res row pair (I, I+1)
        const int Jb = (t & 63) << 5;
        const int B  = Jb >> 3;             // first packed word of span

        // ONE warp-wide LDG: 30 lanes fetch the 5x6 word block
        unsigned W = __ldg(g_pimg + (size_t)refl(I - 2 + lrow) * PSTRIDE + B + lwrd);

        // Redistribute: rc[i] = words (B+ssub, B+ssub+1) of row I-2+i, >> sh
        unsigned rc[6];
        #pragma unroll
        for (int i = 0; i < 6; i++) {
            unsigned w0 = __shfl_sync(0xffffffffu, W, i * 5 + ssub);
            unsigned w1 = __shfl_sync(0xffffffffu, W, i * 5 + ssub + 1);
            rc[i] = __funnelshift_r(w0, w1, sh);
        }

        float acc[2][4];
        #pragma unroll
        for (int ro = 0; ro < 2; ro++)
            acc[ro][0] = acc[ro][1] = acc[ro][2] = acc[ro][3] = 0.f;

        // Pre-scaled nibble extraction: value<<tt, one SHF + one LOP3.
        #define EX(v, jj, tt) \
            (((4*(jj) >= (tt)) ? ((v) >> (4*(jj) - (tt)))               \
                               : ((v) << ((tt) - 4*(jj)))) & (15u << (tt)))

        #define GOFF(ro, k, bx, by, cx, cy)                              \
            (a11 + (unsigned)((k) * 32768) +                             \
             EX(rc[2 + (ro) + (bx)], 2 + (by), 7) +                      \
             EX(rc[2 + (ro) + (cx)], 2 + (cy), 3))

        #define ROT3(ro, b0x,b0y,c0x,c0y, b1x,b1y,c1x,c1y, b2x,b2y,c2x,c2y, \
                     i00,i01,i10,i11) do {                                  \
            uint2 h0 = *reinterpret_cast<const uint2*>(                     \
                           lutb + GOFF(ro, 0, b0x,b0y, c0x,c0y));           \
            uint2 h1 = *reinterpret_cast<const uint2*>(                     \
                           lutb + GOFF(ro, 1, b1x,b1y, c1x,c1y));           \
            uint2 h2 = *reinterpret_cast<const uint2*>(                     \
                           lutb + GOFF(ro, 2, b2x,b2y, c2x,c2y));           \
            __half2 sA = __hadd2(__hadd2(u2h(h0.x), u2h(h1.x)), u2h(h2.x)); \
            __half2 sB = __hadd2(__hadd2(u2h(h0.y), u2h(h1.y)), u2h(h2.y)); \
            float2 fA = __half22float2(sA);                                 \
            float2 fB = __half22float2(sB);                                 \
            float fv[4] = {fA.x, fA.y, fB.x, fB.y};                         \
            acc[ro][0] += fv[i00]; acc[ro][1] += fv[i01];                   \
            acc[ro][2] += fv[i10]; acc[ro][3] += fv[i11];                   \
        } while (0)

        #pragma unroll
        for (int ro = 0; ro < 2; ro++) {
            const unsigned a11 = (rc[2 + ro] << 3) & (15u << 11);
            // r = 0: offsets as-is       perm (0,1,2,3)
            ROT3(ro,  0, 1,  0, 2,   1, 1,  2, 2,   1, 2,  2, 1,  0,1,2,3);
            // r = 1: (x,y)->(y,-x)       perm (2,0,3,1)
            ROT3(ro,  1, 0,  2, 0,   1,-1,  2,-2,   2,-1,  1,-2,  2,0,3,1);
            // r = 2: (x,y)->(-x,-y)      perm (3,2,1,0)
            ROT3(ro,  0,-1,  0,-2,  -1,-1, -2,-2,  -1,-2, -2,-1,  3,2,1,0);
            // r = 3: (x,y)->(-y,x)       perm (1,3,0,2)
            ROT3(ro, -1, 0, -2, 0,  -1, 1, -2, 2,  -2, 1, -1, 2,  1,3,0,2);
        }

        #undef ROT3
        #undef GOFF
        #undef EX

        const int J = Jb + lane;
        const size_t base = (size_t)(2 * I) * 2048 + J;
        out[base        ] = make_float2(acc[0][0], acc[0][1]);
        out[base + 2048 ] = make_float2(acc[0][2], acc[0][3]);
        out[base + 4096 ] = make_float2(acc[1][0], acc[1][1]);
        out[base + 6144 ] = make_float2(acc[1][2], acc[1][3]);
    }
}

extern "C" void kernel_launch(void* const* d_in, const int* in_sizes, int n_in,
                              void* d_out, int out_size)
{
    const int*    img  = (const int*)d_in[0];
    const float4* wlut = (const float4*)d_in[1];
    float2*       out  = (float2*)d_out;

    int sms = 0;
    cudaDeviceGetAttribute(&sms, cudaDevAttrMultiProcessorCount, 0);
    if (sms <= 0) sms = 148;

    hdblut_prelude<<<NN + (LUT_E + 255) / 256, 256>>>(img, wlut);

    cudaFuncSetAttribute(hdblut_main,
                         cudaFuncAttributeMaxDynamicSharedMemorySize, SMEM_BYTES);
    hdblut_main<<<2 * sms, THREADS, SMEM_BYTES>>>(out);
}

// round 14
// speedup vs baseline: 1.0201x; 1.0201x over previous
#include <cuda_runtime.h>
#include <cuda_fp16.h>

// HDBLUT 2x superresolution, GB300 sm_103a. Round 14:
//  - prelude = image nibble-pack only
//  - main kernel launched with PDL (programmatic stream serialization):
//    starts during the pack kernel, fills 96KB smem LUT directly from
//    msb_weight (fp32->fp16, 1/3 folded, independent of prelude), then
//    cudaGridDependencySynchronize() before reading the packed image
//  - R12 gather core (byte-offset addressing) at 2 CTAs/SM x 512 threads

#define NN 2048
#define NTILES (1024 * 64)        // row-pairs x 32-col tiles
#define THREADS 512
#define WARPS_PER_CTA (THREADS / 32)
#define LUT_E (3 * 4096)
#define PSTRIDE 260
#define PWORDS 257
#define SMEM_BYTES (LUT_E * 8)

__device__ unsigned g_pimg[NN * PSTRIDE];      // nibble-packed image

__device__ __forceinline__ int refl(int t) {
    t = (t < 0) ? -t : t;
    return (t >= NN) ? (2 * NN - 2 - t) : t;
}

__device__ __forceinline__ __half2 u2h(unsigned u) {
    return *reinterpret_cast<__half2*>(&u);
}

// One block per image row: int4 loads staged through smem, nibble-pack with
// reflection baked in.
__global__ void hdblut_pack(const int* __restrict__ img)
{
    __shared__ int srow[2056];
    const int tid = threadIdx.x;
    const int r = blockIdx.x;

    const int4* row4 = reinterpret_cast<const int4*>(img + (size_t)r * NN);
    #pragma unroll
    for (int k = 0; k < 2; k++) {
        int i = tid + k * 256;
        int4 v = __ldg(row4 + i);
        srow[2 + i * 4 + 0] = v.x;
        srow[2 + i * 4 + 1] = v.y;
        srow[2 + i * 4 + 2] = v.z;
        srow[2 + i * 4 + 3] = v.w;
    }
    __syncthreads();
    if (tid == 0) {
        srow[0] = srow[4];
        srow[1] = srow[3];
        #pragma unroll
        for (int i = 0; i < 6; i++)
            srow[2050 + i] = srow[2048 - i];
    }
    __syncthreads();
    for (int wi = tid; wi < PWORDS; wi += 256) {
        const int* s = srow + wi * 8;
        unsigned val = 0;
        #pragma unroll
        for (int j = 0; j < 8; j++)
            val |= (unsigned)(s[j] & 15) << (4 * j);
        g_pimg[(size_t)r * PSTRIDE + wi] = val;
    }
}

__global__ __launch_bounds__(THREADS, 2)
void hdblut_main(const float4* __restrict__ wlut, float2* __restrict__ out)
{
    extern __shared__ uint2 slut[];   // 96 KB fp16 LUT (1/3 folded)

    // Fill smem LUT straight from gmem fp32 — independent of the pack
    // kernel, so it overlaps it under PDL.
    for (int i = threadIdx.x; i < LUT_E; i += THREADS) {
        float4 v = __ldg(wlut + i);
        const float s = 1.0f / 3.0f;
        __half2 lo = __floats2half2_rn(v.x * s, v.y * s);
        __half2 hi = __floats2half2_rn(v.z * s, v.w * s);
        uint2 u;
        u.x = *reinterpret_cast<unsigned*>(&lo);
        u.y = *reinterpret_cast<unsigned*>(&hi);
        slut[i] = u;
    }

    // Wait for the pack kernel before touching g_pimg.
#if __CUDA_ARCH__ >= 900
    cudaGridDependencySynchronize();
#endif
    __syncthreads();

    const char* lutb = reinterpret_cast<const char*>(slut);
    const int warp = threadIdx.x >> 5;
    const int lane = threadIdx.x & 31;
    const int gwarp  = blockIdx.x * WARPS_PER_CTA + warp;
    const int nwarps = gridDim.x * WARPS_PER_CTA;

    for (int t = gwarp; t < NTILES; t += nwarps) {
        const int I  = (t >> 6) << 1;       // low-res row pair (I, I+1)
        const int Jb = (t & 63) << 5;

        // 6 packed rows I-2..I+3; nibble j of rc[i] = img col J-2+j (J=Jb+lane)
        unsigned rc[6];
        {
            const int pos = Jb + lane;
            const int wi  = pos >> 3;
            const int sh  = (pos & 7) * 4;
            #pragma unroll
            for (int i = 0; i < 6; i++) {
                const unsigned* pr = g_pimg + (size_t)refl(I - 2 + i) * PSTRIDE + wi;
                unsigned w0 = __ldg(pr);
                unsigned w1 = __ldg(pr + 1);
                rc[i] = __funnelshift_r(w0, w1, sh);
            }
        }

        float acc[2][4];
        #pragma unroll
        for (int ro = 0; ro < 2; ro++)
            acc[ro][0] = acc[ro][1] = acc[ro][2] = acc[ro][3] = 0.f;

        // Pre-scaled nibble extraction: value<<tt, one SHF + one LOP3.
        #define EX(v, jj, tt) \
            (((4*(jj) >= (tt)) ? ((v) >> (4*(jj) - (tt)))               \
                               : ((v) << ((tt) - 4*(jj)))) & (15u << (tt)))

        #define GOFF(ro, k, bx, by, cx, cy)                              \
            (a11 + (unsigned)((k) * 32768) +                             \
             EX(rc[2 + (ro) + (bx)], 2 + (by), 7) +                      \
             EX(rc[2 + (ro) + (cx)], 2 + (cy), 3))

        #define ROT3(ro, b0x,b0y,c0x,c0y, b1x,b1y,c1x,c1y, b2x,b2y,c2x,c2y, \
                     i00,i01,i10,i11) do {                                  \
            uint2 h0 = *reinterpret_cast<const uint2*>(                     \
                           lutb + GOFF(ro, 0, b0x,b0y, c0x,c0y));           \
            uint2 h1 = *reinterpret_cast<const uint2*>(                     \
                           lutb + GOFF(ro, 1, b1x,b1y, c1x,c1y));           \
            uint2 h2 = *reinterpret_cast<const uint2*>(                     \
                           lutb + GOFF(ro, 2, b2x,b2y, c2x,c2y));           \
            __half2 sA = __hadd2(__hadd2(u2h(h0.x), u2h(h1.x)), u2h(h2.x)); \
            __half2 sB = __hadd2(__hadd2(u2h(h0.y), u2h(h1.y)), u2h(h2.y)); \
            float2 fA = __half22float2(sA);                                 \
            float2 fB = __half22float2(sB);                                 \
            float fv[4] = {fA.x, fA.y, fB.x, fB.y};                         \
            acc[ro][0] += fv[i00]; acc[ro][1] += fv[i01];                   \
            acc[ro][2] += fv[i10]; acc[ro][3] += fv[i11];                   \
        } while (0)

        #pragma unroll
        for (int ro = 0; ro < 2; ro++) {
            const unsigned a11 = (rc[2 + ro] << 3) & (15u << 11);
            // r = 0: offsets as-is       perm (0,1,2,3)
            ROT3(ro,  0, 1,  0, 2,   1, 1,  2, 2,   1, 2,  2, 1,  0,1,2,3);
            // r = 1: (x,y)->(y,-x)       perm (2,0,3,1)
            ROT3(ro,  1, 0,  2, 0,   1,-1,  2,-2,   2,-1,  1,-2,  2,0,3,1);
            // r = 2: (x,y)->(-x,-y)      perm (3,2,1,0)
            ROT3(ro,  0,-1,  0,-2,  -1,-1, -2,-2,  -1,-2, -2,-1,  3,2,1,0);
            // r = 3: (x,y)->(-y,x)       perm (1,3,0,2)
            ROT3(ro, -1, 0, -2, 0,  -1, 1, -2, 2,  -2, 1, -1, 2,  1,3,0,2);
        }

        #undef ROT3
        #undef GOFF
        #undef EX

        const int J = Jb + lane;
        const size_t base = (size_t)(2 * I) * 2048 + J;
        out[base        ] = make_float2(acc[0][0], acc[0][1]);
        out[base + 2048 ] = make_float2(acc[0][2], acc[0][3]);
        out[base + 4096 ] = make_float2(acc[1][0], acc[1][1]);
        out[base + 6144 ] = make_float2(acc[1][2], acc[1][3]);
    }
}

extern "C" void kernel_launch(void* const* d_in, const int* in_sizes, int n_in,
                              void* d_out, int out_size)
{
    const int*    img  = (const int*)d_in[0];
    const float4* wlut = (const float4*)d_in[1];
    float2*       out  = (float2*)d_out;

    int sms = 0;
    cudaDeviceGetAttribute(&sms, cudaDevAttrMultiProcessorCount, 0);
    if (sms <= 0) sms = 148;

    hdblut_pack<<<NN, 256>>>(img);

    cudaFuncSetAttribute(hdblut_main,
                         cudaFuncAttributeMaxDynamicSharedMemorySize, SMEM_BYTES);

    // PDL: main starts while pack runs; gridDepSync orders g_pimg reads.
    cudaLaunchConfig_t cfg = {};
    cfg.gridDim  = dim3(2 * sms, 1, 1);
    cfg.blockDim = dim3(THREADS, 1, 1);
    cfg.dynamicSmemBytes = SMEM_BYTES;
    cfg.stream = 0;
    cudaLaunchAttribute attrs[1];
    attrs[0].id = cudaLaunchAttributeProgrammaticStreamSerialization;
    attrs[0].val.programmaticStreamSerializationAllowed = 1;
    cfg.attrs = attrs;
    cfg.numAttrs = 1;
    cudaLaunchKernelEx(&cfg, hdblut_main, wlut, out);
}